// round 15
// baseline (speedup 1.0000x reference)
#include <cuda_runtime.h>
#include <cstdint>
#include <cuda_fp16.h>
#include <mma.h>
using namespace nvcuda;

// Problem constants
#define Bb 2
#define Tt 16
#define Hh 32
#define Ww 32
#define Cc 768
#define NHh 12
#define HDd 64
#define NTOK (Bb*Tt*Hh*Ww)      // 32768
#define F3 (3*Cc)               // 2304

// Scratch (no allocations allowed — device globals)
__device__ __half g_yh[NTOK * Cc];      // LN output (half)
__device__ __half g_qkvh[NTOK * F3];    // QKV GEMM output (half)
__device__ __half g_oh[NTOK * Cc];      // attention output (half)
__device__ __half g_wqh[F3 * Cc];       // half Wqkv
__device__ __half g_woh[Cc * Cc];       // half Wout

// ---------------------------------------------------------------------------
// float -> half conversion pre-pass
// ---------------------------------------------------------------------------
__global__ void f2h_kernel(const float* __restrict__ in,
                           __half* __restrict__ out, int n4) {
    int i = blockIdx.x * 256 + threadIdx.x;
    if (i < n4) {
        float4 v = ((const float4*)in)[i];
        ((__half2*)out)[2 * i]     = __floats2half2_rn(v.x, v.y);
        ((__half2*)out)[2 * i + 1] = __floats2half2_rn(v.z, v.w);
    }
}

// ---------------------------------------------------------------------------
// LayerNorm (float input): one block (192 threads) per token; half output
// ---------------------------------------------------------------------------
__global__ void ln_kernel(const float* __restrict__ x,
                          const float* __restrict__ w,
                          const float* __restrict__ b,
                          __half* __restrict__ y) {
    int tok = blockIdx.x;
    int t = threadIdx.x;
    const float4* xr = (const float4*)(x + (size_t)tok * Cc);
    __half2* yr = (__half2*)(y + (size_t)tok * Cc);

    float4 v = xr[t];
    float s  = v.x + v.y + v.z + v.w;
    float ss = v.x*v.x + v.y*v.y + v.z*v.z + v.w*v.w;

    __shared__ float reds[6], redss[6];
    #pragma unroll
    for (int o = 16; o; o >>= 1) {
        s  += __shfl_xor_sync(0xffffffffu, s,  o);
        ss += __shfl_xor_sync(0xffffffffu, ss, o);
    }
    int wid = t >> 5, lid = t & 31;
    if (lid == 0) { reds[wid] = s; redss[wid] = ss; }
    __syncthreads();
    if (t < 32) {
        s  = (lid < 6) ? reds[lid]  : 0.f;
        ss = (lid < 6) ? redss[lid] : 0.f;
        #pragma unroll
        for (int o = 4; o; o >>= 1) {
            s  += __shfl_xor_sync(0xffffffffu, s,  o);
            ss += __shfl_xor_sync(0xffffffffu, ss, o);
        }
        if (lid == 0) { reds[0] = s; redss[0] = ss; }
    }
    __syncthreads();
    float mu  = reds[0] * (1.0f / Cc);
    float var = redss[0] * (1.0f / Cc) - mu * mu;
    float rstd = rsqrtf(var + 1e-5f);

    float4 wv = ((const float4*)w)[t];
    float4 bv = ((const float4*)b)[t];
    float rx = (v.x - mu) * rstd * wv.x + bv.x;
    float ry = (v.y - mu) * rstd * wv.y + bv.y;
    float rz = (v.z - mu) * rstd * wv.z + bv.z;
    float rw = (v.w - mu) * rstd * wv.w + bv.w;
    yr[2 * t]     = __floats2half2_rn(rx, ry);
    yr[2 * t + 1] = __floats2half2_rn(rz, rw);
}

// ---------------------------------------------------------------------------
// LayerNorm (half input): one block (192 threads) per token; half output
// ---------------------------------------------------------------------------
__global__ void ln_h_kernel(const __half* __restrict__ x,
                            const float* __restrict__ w,
                            const float* __restrict__ b,
                            __half* __restrict__ y) {
    int tok = blockIdx.x;
    int t = threadIdx.x;
    const __half2* xr = (const __half2*)(x + (size_t)tok * Cc);
    __half2* yr = (__half2*)(y + (size_t)tok * Cc);

    float2 a = __half22float2(xr[2 * t]);
    float2 c = __half22float2(xr[2 * t + 1]);
    float s  = a.x + a.y + c.x + c.y;
    float ss = a.x*a.x + a.y*a.y + c.x*c.x + c.y*c.y;

    __shared__ float reds[6], redss[6];
    #pragma unroll
    for (int o = 16; o; o >>= 1) {
        s  += __shfl_xor_sync(0xffffffffu, s,  o);
        ss += __shfl_xor_sync(0xffffffffu, ss, o);
    }
    int wid = t >> 5, lid = t & 31;
    if (lid == 0) { reds[wid] = s; redss[wid] = ss; }
    __syncthreads();
    if (t < 32) {
        s  = (lid < 6) ? reds[lid]  : 0.f;
        ss = (lid < 6) ? redss[lid] : 0.f;
        #pragma unroll
        for (int o = 4; o; o >>= 1) {
            s  += __shfl_xor_sync(0xffffffffu, s,  o);
            ss += __shfl_xor_sync(0xffffffffu, ss, o);
        }
        if (lid == 0) { reds[0] = s; redss[0] = ss; }
    }
    __syncthreads();
    float mu  = reds[0] * (1.0f / Cc);
    float var = redss[0] * (1.0f / Cc) - mu * mu;
    float rstd = rsqrtf(var + 1e-5f);

    float4 wv = ((const float4*)w)[t];
    float4 bv = ((const float4*)b)[t];
    float rx = (a.x - mu) * rstd * wv.x + bv.x;
    float ry = (a.y - mu) * rstd * wv.y + bv.y;
    float rz = (c.x - mu) * rstd * wv.z + bv.z;
    float rw = (c.y - mu) * rstd * wv.w + bv.w;
    yr[2 * t]     = __floats2half2_rn(rx, ry);
    yr[2 * t + 1] = __floats2half2_rn(rz, rw);
}

// ---------------------------------------------------------------------------
// FP16 wmma GEMM (fp32 accumulate), 4-stage cp.async, 1 barrier/iter,
// register double-buffered fragments (kk+16 loads issued before kk MMAs).
// Block 128x128, 8 warps (2m x 4n), warp tile 64x32. BK=32 halfs. 1 CTA/SM.
// ---------------------------------------------------------------------------
#define BM 128
#define BN 128
#define BKH 32
#define SSTRH 40
#define LDC 132
#define STAGES 4
#define NTHR 256
#define STAGE_H ((BM + BN) * SSTRH)            // 10240 halfs = 20480 B
#define PIPE_BYTES (STAGES * STAGE_H * 2)      // 81920
#define EPI_BYTES (BM * LDC * 4)               // 67584
#define GEMM_SMEM_BYTES (EPI_BYTES > PIPE_BYTES ? EPI_BYTES : PIPE_BYTES)

__device__ __forceinline__ void cp_async16(void* smem_dst, const void* gmem_src) {
    unsigned s = (unsigned)__cvta_generic_to_shared(smem_dst);
    asm volatile("cp.async.cg.shared.global [%0], [%1], 16;\n" :: "r"(s), "l"(gmem_src));
}
#define CP_COMMIT() asm volatile("cp.async.commit_group;\n" ::: "memory")
#define CP_WAIT_N(n) asm volatile("cp.async.wait_group %0;\n" :: "n"(n) : "memory")

typedef wmma::fragment<wmma::matrix_a, 16, 16, 16, __half, wmma::row_major> AFrag;
typedef wmma::fragment<wmma::matrix_b, 16, 16, 16, __half, wmma::col_major> BFrag;
typedef wmma::fragment<wmma::accumulator, 16, 16, 16, float> CFrag;

template <bool RES, bool OUTH>
__global__ void __launch_bounds__(NTHR, 1) gemm_fp16(
        const __half* __restrict__ A,
        const __half* __restrict__ Wt,
        const float* __restrict__ bias,
        const float* __restrict__ res,
        float* __restrict__ Cout,
        __half* __restrict__ CoutH,
        int N, int K) {
    extern __shared__ __align__(16) char smem_raw[];
    __half* hs = (__half*)smem_raw;

    int tid = threadIdx.x;
    int m0 = blockIdx.y * BM;
    int n0 = blockIdx.x * BN;

    // load mapping: 2 threads per row, 2 x 16B chunks each
    int lrow = tid >> 1;
    int lc0  = (tid & 1) * 2;

    const __half* Abase = A  + (size_t)(m0 + lrow) * K + lc0 * 8;
    const __half* Bbase = Wt + (size_t)(n0 + lrow) * K + lc0 * 8;

    int wid = tid >> 5;
    int wm = (wid & 1) * 64;             // 2 warps m
    int wn = (wid >> 1) * 32;            // 4 warps n

    CFrag acc[4][2];
    #pragma unroll
    for (int i = 0; i < 4; i++)
        #pragma unroll
        for (int j = 0; j < 2; j++)
            wmma::fill_fragment(acc[i][j], 0.0f);

    const int nit = K / BKH;             // 24

    #pragma unroll
    for (int s = 0; s < STAGES - 1; s++) {
        __half* a = hs + s * STAGE_H + lrow * SSTRH + lc0 * 8;
        __half* b = hs + s * STAGE_H + BM * SSTRH + lrow * SSTRH + lc0 * 8;
        const __half* ag = Abase + s * BKH;
        const __half* bg = Bbase + s * BKH;
        #pragma unroll
        for (int c = 0; c < 2; c++) {
            cp_async16(a + c * 8, ag + c * 8);
            cp_async16(b + c * 8, bg + c * 8);
        }
        CP_COMMIT();
    }

    AFrag af0[4], af1[4];
    BFrag bf0[2], bf1[2];

    int sc_ = 0, sl_ = STAGES - 1;
    for (int it = 0; it < nit; it++) {
        CP_WAIT_N(STAGES - 2);
        __syncthreads();

        __half* Ac = hs + sc_ * STAGE_H;
        __half* Bc = Ac + BM * SSTRH;

        // Issue fragment loads for kk=0 (buffer 0) immediately after barrier.
        #pragma unroll
        for (int i = 0; i < 4; i++)
            wmma::load_matrix_sync(af0[i], &Ac[(wm + i * 16) * SSTRH], SSTRH);
        #pragma unroll
        for (int j = 0; j < 2; j++)
            wmma::load_matrix_sync(bf0[j], &Bc[(wn + j * 16) * SSTRH], SSTRH);

        // Refill stage sl_ (freed at it-1; safe after the barrier above)
        if (it + STAGES - 1 < nit) {
            __half* a = hs + sl_ * STAGE_H + lrow * SSTRH + lc0 * 8;
            __half* b = hs + sl_ * STAGE_H + BM * SSTRH + lrow * SSTRH + lc0 * 8;
            const __half* ag = Abase + (it + STAGES - 1) * BKH;
            const __half* bg = Bbase + (it + STAGES - 1) * BKH;
            #pragma unroll
            for (int c = 0; c < 2; c++) {
                cp_async16(a + c * 8, ag + c * 8);
                cp_async16(b + c * 8, bg + c * 8);
            }
        }
        CP_COMMIT();

        // Issue fragment loads for kk=16 (buffer 1) BEFORE kk=0 MMAs so their
        // smem latency hides under the tensor work.
        #pragma unroll
        for (int i = 0; i < 4; i++)
            wmma::load_matrix_sync(af1[i], &Ac[(wm + i * 16) * SSTRH + 16], SSTRH);
        #pragma unroll
        for (int j = 0; j < 2; j++)
            wmma::load_matrix_sync(bf1[j], &Bc[(wn + j * 16) * SSTRH + 16], SSTRH);

        // MMA kk=0
        #pragma unroll
        for (int i = 0; i < 4; i++)
            #pragma unroll
            for (int j = 0; j < 2; j++)
                wmma::mma_sync(acc[i][j], af0[i], bf0[j], acc[i][j]);
        // MMA kk=16
        #pragma unroll
        for (int i = 0; i < 4; i++)
            #pragma unroll
            for (int j = 0; j < 2; j++)
                wmma::mma_sync(acc[i][j], af1[i], bf1[j], acc[i][j]);

        sc_ = (sc_ + 1 == STAGES) ? 0 : sc_ + 1;
        sl_ = (sl_ + 1 == STAGES) ? 0 : sl_ + 1;
    }
    CP_WAIT_N(0);
    __syncthreads();

    // Epilogue through shared (fp32)
    float* Cs = (float*)smem_raw;
    #pragma unroll
    for (int i = 0; i < 4; i++)
        #pragma unroll
        for (int j = 0; j < 2; j++)
            wmma::store_matrix_sync(&Cs[(wm + i * 16) * LDC + wn + j * 16],
                                    acc[i][j], LDC, wmma::mem_row_major);
    __syncthreads();

    if (OUTH) {
        #pragma unroll
        for (int i = 0; i < 32; i++) {
            int idx = tid + i * NTHR;
            int r = idx >> 6, c2 = idx & 63;
            float2 cs = *(const float2*)&Cs[r * LDC + c2 * 2];
            float2 bv = *(const float2*)(bias + n0 + c2 * 2);
            __half2 hv = __floats2half2_rn(cs.x + bv.x, cs.y + bv.y);
            *((__half2*)(CoutH + (size_t)(m0 + r) * N + n0) + c2) = hv;
        }
    } else {
        #pragma unroll
        for (int i = 0; i < 16; i++) {
            int idx = tid + i * NTHR;
            int r = idx >> 5, c4 = idx & 31;
            const float* cs = &Cs[r * LDC + c4 * 4];
            float4 bv = *(const float4*)(bias + n0 + c4 * 4);
            float4 v;
            v.x = cs[0] + bv.x; v.y = cs[1] + bv.y;
            v.z = cs[2] + bv.z; v.w = cs[3] + bv.w;
            size_t g = (size_t)(m0 + r) * N + n0 + c4 * 4;
            if (RES) {
                float4 rv = *(const float4*)(res + g);
                v.x += rv.x; v.y += rv.y; v.z += rv.z; v.w += rv.w;
            }
            *(float4*)(Cout + g) = v;
        }
    }
}

// ---------------------------------------------------------------------------
// Attention over time axis: one warp per (b,h,w,head) unit. T=16, HD=64.
// Half input (qkv), half output (o). Softmax/accum in fp32.
// ---------------------------------------------------------------------------
__global__ void attn_kernel(const __half* __restrict__ qkv,
                            __half* __restrict__ o) {
    int warp_in_blk = threadIdx.x >> 5;
    int lane = threadIdx.x & 31;
    int unit = blockIdx.x * 2 + warp_in_blk;   // 2 warps per block

    __shared__ __half2 sh2[2][3 * 16 * 36];    // q,k,v per warp
    __shared__ float sp[2][16 * 17];           // probs per warp
    __half2* q = sh2[warp_in_blk];
    __half2* k = q + 16 * 36;
    __half2* v = k + 16 * 36;
    float* p = sp[warp_in_blk];

    int head = unit % NHh;
    int s = unit / NHh;
    int w = s & 31; s >>= 5;
    int h = s & 31;
    int b = s >> 5;

    int spatial = h * 32 + w;

    // Load q,k,v (16 rows x 32 half2 each)
    for (int i = lane; i < 16 * 32; i += 32) {
        int t = i >> 5, d2 = i & 31;
        size_t g = ((size_t)((b * 16 + t) * 1024 + spatial)) * F3 + head * 192;
        const __half2* p2 = (const __half2*)(qkv + g);
        q[t * 36 + d2] = p2[d2];
        k[t * 36 + d2] = p2[32 + d2];
        v[t * 36 + d2] = p2[64 + d2];
    }
    __syncwarp();

    // Scores: lane pair per tq; each lane 8 tk
    int tq = lane >> 1;
    int tk0 = (lane & 1) * 8;
    float sc[8];
    #pragma unroll
    for (int j = 0; j < 8; j++) {
        float acc = 0.f;
        #pragma unroll
        for (int d2 = 0; d2 < 32; d2++) {
            float2 qf = __half22float2(q[tq * 36 + d2]);
            float2 kf = __half22float2(k[(tk0 + j) * 36 + d2]);
            acc += qf.x * kf.x + qf.y * kf.y;
        }
        sc[j] = acc * 0.125f;
    }
    float m = sc[0];
    #pragma unroll
    for (int j = 1; j < 8; j++) m = fmaxf(m, sc[j]);
    m = fmaxf(m, __shfl_xor_sync(0xffffffffu, m, 1));
    float sum = 0.f;
    #pragma unroll
    for (int j = 0; j < 8; j++) { sc[j] = __expf(sc[j] - m); sum += sc[j]; }
    sum += __shfl_xor_sync(0xffffffffu, sum, 1);
    float inv = 1.0f / sum;
    #pragma unroll
    for (int j = 0; j < 8; j++) p[tq * 17 + tk0 + j] = sc[j] * inv;
    __syncwarp();

    // o[t, d2=lane]: loop t; accumulate over tk in fp32; write half2
    for (int t = 0; t < 16; t++) {
        float2 acc = make_float2(0.f, 0.f);
        #pragma unroll
        for (int tk = 0; tk < 16; tk++) {
            float pw = p[t * 17 + tk];
            float2 vf = __half22float2(v[tk * 36 + lane]);
            acc.x += pw * vf.x;
            acc.y += pw * vf.y;
        }
        size_t g = ((size_t)((b * 16 + t) * 1024 + spatial)) * Cc + head * 64;
        *((__half2*)(o + g) + lane) = __floats2half2_rn(acc.x, acc.y);
    }
}

// ---------------------------------------------------------------------------
// Launch
// ---------------------------------------------------------------------------
extern "C" void kernel_launch(void* const* d_in, const int* in_sizes, int n_in,
                              void* d_out, int out_size) {
    const float* x     = (const float*)d_in[0];
    const float* ln1_w = (const float*)d_in[1];
    const float* ln1_b = (const float*)d_in[2];
    const float* Wqkv  = (const float*)d_in[3];
    const float* bqkv  = (const float*)d_in[4];
    const float* ln2_w = (const float*)d_in[5];
    const float* ln2_b = (const float*)d_in[6];
    const float* Wout  = (const float*)d_in[7];
    const float* bout  = (const float*)d_in[8];
    float* out = (float*)d_out;

    static __half *p_yh = nullptr, *p_qkvh = nullptr, *p_oh = nullptr,
                  *p_wqh = nullptr, *p_woh = nullptr;
    if (!p_yh) {
        cudaGetSymbolAddress((void**)&p_yh, g_yh);
        cudaGetSymbolAddress((void**)&p_qkvh, g_qkvh);
        cudaGetSymbolAddress((void**)&p_oh, g_oh);
        cudaGetSymbolAddress((void**)&p_wqh, g_wqh);
        cudaGetSymbolAddress((void**)&p_woh, g_woh);
        cudaFuncSetAttribute((const void*)gemm_fp16<false, true>,
                             cudaFuncAttributeMaxDynamicSharedMemorySize, GEMM_SMEM_BYTES);
        cudaFuncSetAttribute((const void*)gemm_fp16<true, false>,
                             cudaFuncAttributeMaxDynamicSharedMemorySize, GEMM_SMEM_BYTES);
    }

    // 0) weights -> half
    {
        int n4q = (F3 * Cc) / 4, n4o = (Cc * Cc) / 4;
        f2h_kernel<<<(n4q + 255) / 256, 256>>>(Wqkv, p_wqh, n4q);
        f2h_kernel<<<(n4o + 255) / 256, 256>>>(Wout, p_woh, n4o);
    }

    // 1) LN1 -> half
    ln_kernel<<<NTOK, 192>>>(x, ln1_w, ln1_b, p_yh);

    // 2) QKV GEMM (half output): (32768 x 2304)
    {
        dim3 grid(F3 / BN, NTOK / BM);     // 18 x 256
        gemm_fp16<false, true><<<grid, NTHR, GEMM_SMEM_BYTES>>>(
            p_yh, p_wqh, bqkv, nullptr, nullptr, p_qkvh, F3, Cc);
    }

    // 3) Attention (half in/out)
    {
        int nunits = Bb * Hh * Ww * NHh;   // 24576
        attn_kernel<<<nunits / 2, 64>>>(p_qkvh, p_oh);
    }

    // 4) LN2 (half in) -> half y
    ln_h_kernel<<<NTOK, 192>>>(p_oh, ln2_w, ln2_b, p_yh);

    // 5) Out GEMM + bias + residual: (32768 x 768), float output
    {
        dim3 grid(Cc / BN, NTOK / BM);     // 6 x 256
        gemm_fp16<true, false><<<grid, NTHR, GEMM_SMEM_BYTES>>>(
            p_yh, p_woh, bout, x, out, nullptr, Cc, Cc);
    }
}

// round 16
// speedup vs baseline: 1.1439x; 1.1439x over previous
#include <cuda_runtime.h>
#include <cstdint>
#include <cuda_fp16.h>
#include <mma.h>
using namespace nvcuda;

// Problem constants
#define Bb 2
#define Tt 16
#define Hh 32
#define Ww 32
#define Cc 768
#define NHh 12
#define HDd 64
#define NTOK (Bb*Tt*Hh*Ww)      // 32768
#define F3 (3*Cc)               // 2304

// Scratch (no allocations allowed — device globals)
__device__ __half g_yh[NTOK * Cc];      // LN output (half)
__device__ __half g_qkvh[NTOK * F3];    // QKV GEMM output (half)
__device__ __half g_oh[NTOK * Cc];      // attention output (half)
__device__ __half g_wqh[F3 * Cc];       // half Wqkv
__device__ __half g_woh[Cc * Cc];       // half Wout

// ---------------------------------------------------------------------------
// float -> half conversion pre-pass
// ---------------------------------------------------------------------------
__global__ void f2h_kernel(const float* __restrict__ in,
                           __half* __restrict__ out, int n4) {
    int i = blockIdx.x * 256 + threadIdx.x;
    if (i < n4) {
        float4 v = ((const float4*)in)[i];
        ((__half2*)out)[2 * i]     = __floats2half2_rn(v.x, v.y);
        ((__half2*)out)[2 * i + 1] = __floats2half2_rn(v.z, v.w);
    }
}

// ---------------------------------------------------------------------------
// LayerNorm (float input): one block (192 threads) per token; half output
// ---------------------------------------------------------------------------
__global__ void ln_kernel(const float* __restrict__ x,
                          const float* __restrict__ w,
                          const float* __restrict__ b,
                          __half* __restrict__ y) {
    int tok = blockIdx.x;
    int t = threadIdx.x;
    const float4* xr = (const float4*)(x + (size_t)tok * Cc);
    __half2* yr = (__half2*)(y + (size_t)tok * Cc);

    float4 v = xr[t];
    float s  = v.x + v.y + v.z + v.w;
    float ss = v.x*v.x + v.y*v.y + v.z*v.z + v.w*v.w;

    __shared__ float reds[6], redss[6];
    #pragma unroll
    for (int o = 16; o; o >>= 1) {
        s  += __shfl_xor_sync(0xffffffffu, s,  o);
        ss += __shfl_xor_sync(0xffffffffu, ss, o);
    }
    int wid = t >> 5, lid = t & 31;
    if (lid == 0) { reds[wid] = s; redss[wid] = ss; }
    __syncthreads();
    if (t < 32) {
        s  = (lid < 6) ? reds[lid]  : 0.f;
        ss = (lid < 6) ? redss[lid] : 0.f;
        #pragma unroll
        for (int o = 4; o; o >>= 1) {
            s  += __shfl_xor_sync(0xffffffffu, s,  o);
            ss += __shfl_xor_sync(0xffffffffu, ss, o);
        }
        if (lid == 0) { reds[0] = s; redss[0] = ss; }
    }
    __syncthreads();
    float mu  = reds[0] * (1.0f / Cc);
    float var = redss[0] * (1.0f / Cc) - mu * mu;
    float rstd = rsqrtf(var + 1e-5f);

    float4 wv = ((const float4*)w)[t];
    float4 bv = ((const float4*)b)[t];
    float rx = (v.x - mu) * rstd * wv.x + bv.x;
    float ry = (v.y - mu) * rstd * wv.y + bv.y;
    float rz = (v.z - mu) * rstd * wv.z + bv.z;
    float rw = (v.w - mu) * rstd * wv.w + bv.w;
    yr[2 * t]     = __floats2half2_rn(rx, ry);
    yr[2 * t + 1] = __floats2half2_rn(rz, rw);
}

// ---------------------------------------------------------------------------
// LayerNorm (half input): one block (192 threads) per token; half output
// ---------------------------------------------------------------------------
__global__ void ln_h_kernel(const __half* __restrict__ x,
                            const float* __restrict__ w,
                            const float* __restrict__ b,
                            __half* __restrict__ y) {
    int tok = blockIdx.x;
    int t = threadIdx.x;
    const __half2* xr = (const __half2*)(x + (size_t)tok * Cc);
    __half2* yr = (__half2*)(y + (size_t)tok * Cc);

    float2 a = __half22float2(xr[2 * t]);
    float2 c = __half22float2(xr[2 * t + 1]);
    float s  = a.x + a.y + c.x + c.y;
    float ss = a.x*a.x + a.y*a.y + c.x*c.x + c.y*c.y;

    __shared__ float reds[6], redss[6];
    #pragma unroll
    for (int o = 16; o; o >>= 1) {
        s  += __shfl_xor_sync(0xffffffffu, s,  o);
        ss += __shfl_xor_sync(0xffffffffu, ss, o);
    }
    int wid = t >> 5, lid = t & 31;
    if (lid == 0) { reds[wid] = s; redss[wid] = ss; }
    __syncthreads();
    if (t < 32) {
        s  = (lid < 6) ? reds[lid]  : 0.f;
        ss = (lid < 6) ? redss[lid] : 0.f;
        #pragma unroll
        for (int o = 4; o; o >>= 1) {
            s  += __shfl_xor_sync(0xffffffffu, s,  o);
            ss += __shfl_xor_sync(0xffffffffu, ss, o);
        }
        if (lid == 0) { reds[0] = s; redss[0] = ss; }
    }
    __syncthreads();
    float mu  = reds[0] * (1.0f / Cc);
    float var = redss[0] * (1.0f / Cc) - mu * mu;
    float rstd = rsqrtf(var + 1e-5f);

    float4 wv = ((const float4*)w)[t];
    float4 bv = ((const float4*)b)[t];
    float rx = (a.x - mu) * rstd * wv.x + bv.x;
    float ry = (a.y - mu) * rstd * wv.y + bv.y;
    float rz = (c.x - mu) * rstd * wv.z + bv.z;
    float rw = (c.y - mu) * rstd * wv.w + bv.w;
    yr[2 * t]     = __floats2half2_rn(rx, ry);
    yr[2 * t + 1] = __floats2half2_rn(rz, rw);
}

// ---------------------------------------------------------------------------
// FP16 wmma GEMM (fp32 accumulate), 4-stage cp.async, 1 barrier/iter.
// BMT=128: 8 warps (2m x 4n), 256 thr, 2 CTA/SM.
// BMT=256: 16 warps (4m x 4n), 512 thr, 1 CTA/SM.
// Warp tile 64x32, BK=32 halfs, SSTRH=40.
// ---------------------------------------------------------------------------
#define BN 128
#define BKH 32
#define SSTRH 40
#define LDC 132
#define STAGES 4

__device__ __forceinline__ void cp_async16(void* smem_dst, const void* gmem_src) {
    unsigned s = (unsigned)__cvta_generic_to_shared(smem_dst);
    asm volatile("cp.async.cg.shared.global [%0], [%1], 16;\n" :: "r"(s), "l"(gmem_src));
}
#define CP_COMMIT() asm volatile("cp.async.commit_group;\n" ::: "memory")
#define CP_WAIT_N(n) asm volatile("cp.async.wait_group %0;\n" :: "n"(n) : "memory")

template <int BMT>
constexpr int gemm_smem_bytes() {
    int pipe = STAGES * (BMT + BN) * SSTRH * 2;
    int epi = BMT * LDC * 4;
    return pipe > epi ? pipe : epi;
}

template <int BMT, bool RES, bool OUTH>
__global__ void __launch_bounds__(BMT * 2, BMT == 128 ? 2 : 1) gemm_fp16(
        const __half* __restrict__ A,
        const __half* __restrict__ Wt,
        const float* __restrict__ bias,
        const float* __restrict__ res,
        float* __restrict__ Cout,
        __half* __restrict__ CoutH,
        int N, int K) {
    constexpr int NTHR = BMT * 2;
    constexpr int STAGE_H = (BMT + BN) * SSTRH;
    extern __shared__ __align__(16) char smem_raw[];
    __half* hs = (__half*)smem_raw;

    int tid = threadIdx.x;
    int m0 = blockIdx.y * BMT;
    int n0 = blockIdx.x * BN;

    int wid = tid >> 5;
    int wm, wn;
    if (BMT == 128) { wm = (wid & 1) * 64; wn = (wid >> 1) * 32; }
    else            { wm = (wid & 3) * 64; wn = (wid >> 2) * 32; }

    // Loader mapping
    int lrow, lc0, arow0, aco;
    const __half *Ab0, *Ab1, *Bb0;
    if (BMT == 128) {
        lrow = tid >> 1; lc0 = (tid & 1) * 2;
        Ab0 = A  + (size_t)(m0 + lrow) * K + lc0 * 8;
        Bb0 = Wt + (size_t)(n0 + lrow) * K + lc0 * 8;
        Ab1 = nullptr; arow0 = 0; aco = 0;
    } else {
        arow0 = tid >> 2; aco = (tid & 3) * 8;
        Ab0 = A  + (size_t)(m0 + arow0) * K + aco;
        Ab1 = A  + (size_t)(m0 + arow0 + 128) * K + aco;
        Bb0 = Wt + (size_t)(n0 + arow0) * K + aco;
        lrow = 0; lc0 = 0;
    }

    wmma::fragment<wmma::accumulator, 16, 16, 16, float> acc[4][2];
    #pragma unroll
    for (int i = 0; i < 4; i++)
        #pragma unroll
        for (int j = 0; j < 2; j++)
            wmma::fill_fragment(acc[i][j], 0.0f);

    const int nit = K / BKH;             // 24

    #pragma unroll
    for (int s = 0; s < STAGES - 1; s++) {
        __half* abase = hs + s * STAGE_H;
        __half* bbase = abase + BMT * SSTRH;
        int ko = s * BKH;
        if (BMT == 128) {
            __half* a = abase + lrow * SSTRH + lc0 * 8;
            __half* b = bbase + lrow * SSTRH + lc0 * 8;
            #pragma unroll
            for (int c = 0; c < 2; c++) {
                cp_async16(a + c * 8, Ab0 + ko + c * 8);
                cp_async16(b + c * 8, Bb0 + ko + c * 8);
            }
        } else {
            cp_async16(abase + arow0 * SSTRH + aco,         Ab0 + ko);
            cp_async16(abase + (arow0 + 128) * SSTRH + aco, Ab1 + ko);
            cp_async16(bbase + arow0 * SSTRH + aco,         Bb0 + ko);
        }
        CP_COMMIT();
    }

    int sc_ = 0, sl_ = STAGES - 1;
    for (int it = 0; it < nit; it++) {
        CP_WAIT_N(STAGES - 2);
        __syncthreads();

        if (it + STAGES - 1 < nit) {
            __half* abase = hs + sl_ * STAGE_H;
            __half* bbase = abase + BMT * SSTRH;
            int ko = (it + STAGES - 1) * BKH;
            if (BMT == 128) {
                __half* a = abase + lrow * SSTRH + lc0 * 8;
                __half* b = bbase + lrow * SSTRH + lc0 * 8;
                #pragma unroll
                for (int c = 0; c < 2; c++) {
                    cp_async16(a + c * 8, Ab0 + ko + c * 8);
                    cp_async16(b + c * 8, Bb0 + ko + c * 8);
                }
            } else {
                cp_async16(abase + arow0 * SSTRH + aco,         Ab0 + ko);
                cp_async16(abase + (arow0 + 128) * SSTRH + aco, Ab1 + ko);
                cp_async16(bbase + arow0 * SSTRH + aco,         Bb0 + ko);
            }
        }
        CP_COMMIT();

        __half* Ac = hs + sc_ * STAGE_H;
        __half* Bc = Ac + BMT * SSTRH;
        #pragma unroll
        for (int kk = 0; kk < BKH; kk += 16) {
            wmma::fragment<wmma::matrix_a, 16, 16, 16, __half, wmma::row_major> af[4];
            wmma::fragment<wmma::matrix_b, 16, 16, 16, __half, wmma::col_major> bf[2];
            #pragma unroll
            for (int i = 0; i < 4; i++)
                wmma::load_matrix_sync(af[i], &Ac[(wm + i * 16) * SSTRH + kk], SSTRH);
            #pragma unroll
            for (int j = 0; j < 2; j++)
                wmma::load_matrix_sync(bf[j], &Bc[(wn + j * 16) * SSTRH + kk], SSTRH);
            #pragma unroll
            for (int i = 0; i < 4; i++)
                #pragma unroll
                for (int j = 0; j < 2; j++)
                    wmma::mma_sync(acc[i][j], af[i], bf[j], acc[i][j]);
        }

        sc_ = (sc_ + 1 == STAGES) ? 0 : sc_ + 1;
        sl_ = (sl_ + 1 == STAGES) ? 0 : sl_ + 1;
    }
    CP_WAIT_N(0);
    __syncthreads();

    // Epilogue through shared (fp32)
    float* Cs = (float*)smem_raw;
    #pragma unroll
    for (int i = 0; i < 4; i++)
        #pragma unroll
        for (int j = 0; j < 2; j++)
            wmma::store_matrix_sync(&Cs[(wm + i * 16) * LDC + wn + j * 16],
                                    acc[i][j], LDC, wmma::mem_row_major);
    __syncthreads();

    if (OUTH) {
        // BMT*128 as half2: BMT*64 elems; iters = BMT*64/NTHR = 32
        #pragma unroll
        for (int i = 0; i < 32; i++) {
            int idx = tid + i * NTHR;
            int r = idx >> 6, c2 = idx & 63;
            float2 cs = *(const float2*)&Cs[r * LDC + c2 * 2];
            float2 bv = *(const float2*)(bias + n0 + c2 * 2);
            __half2 hv = __floats2half2_rn(cs.x + bv.x, cs.y + bv.y);
            *((__half2*)(CoutH + (size_t)(m0 + r) * N + n0) + c2) = hv;
        }
    } else {
        // BMT*128 as float4: BMT*32; iters = BMT*32/NTHR = 16
        #pragma unroll
        for (int i = 0; i < 16; i++) {
            int idx = tid + i * NTHR;
            int r = idx >> 5, c4 = idx & 31;
            const float* cs = &Cs[r * LDC + c4 * 4];
            float4 bv = *(const float4*)(bias + n0 + c4 * 4);
            float4 v;
            v.x = cs[0] + bv.x; v.y = cs[1] + bv.y;
            v.z = cs[2] + bv.z; v.w = cs[3] + bv.w;
            size_t g = (size_t)(m0 + r) * N + n0 + c4 * 4;
            if (RES) {
                float4 rv = *(const float4*)(res + g);
                v.x += rv.x; v.y += rv.y; v.z += rv.z; v.w += rv.w;
            }
            *(float4*)(Cout + g) = v;
        }
    }
}

// ---------------------------------------------------------------------------
// Attention over time axis: one warp per (b,h,w,head) unit. T=16, HD=64.
// Half input (qkv), half output (o). Softmax/accum in fp32.
// ---------------------------------------------------------------------------
__global__ void attn_kernel(const __half* __restrict__ qkv,
                            __half* __restrict__ o) {
    int warp_in_blk = threadIdx.x >> 5;
    int lane = threadIdx.x & 31;
    int unit = blockIdx.x * 2 + warp_in_blk;   // 2 warps per block

    __shared__ __half2 sh2[2][3 * 16 * 36];    // q,k,v per warp
    __shared__ float sp[2][16 * 17];           // probs per warp
    __half2* q = sh2[warp_in_blk];
    __half2* k = q + 16 * 36;
    __half2* v = k + 16 * 36;
    float* p = sp[warp_in_blk];

    int head = unit % NHh;
    int s = unit / NHh;
    int w = s & 31; s >>= 5;
    int h = s & 31;
    int b = s >> 5;

    int spatial = h * 32 + w;

    // Load q,k,v (16 rows x 32 half2 each)
    for (int i = lane; i < 16 * 32; i += 32) {
        int t = i >> 5, d2 = i & 31;
        size_t g = ((size_t)((b * 16 + t) * 1024 + spatial)) * F3 + head * 192;
        const __half2* p2 = (const __half2*)(qkv + g);
        q[t * 36 + d2] = p2[d2];
        k[t * 36 + d2] = p2[32 + d2];
        v[t * 36 + d2] = p2[64 + d2];
    }
    __syncwarp();

    // Scores: lane pair per tq; each lane 8 tk
    int tq = lane >> 1;
    int tk0 = (lane & 1) * 8;
    float sc[8];
    #pragma unroll
    for (int j = 0; j < 8; j++) {
        float acc = 0.f;
        #pragma unroll
        for (int d2 = 0; d2 < 32; d2++) {
            float2 qf = __half22float2(q[tq * 36 + d2]);
            float2 kf = __half22float2(k[(tk0 + j) * 36 + d2]);
            acc += qf.x * kf.x + qf.y * kf.y;
        }
        sc[j] = acc * 0.125f;
    }
    float m = sc[0];
    #pragma unroll
    for (int j = 1; j < 8; j++) m = fmaxf(m, sc[j]);
    m = fmaxf(m, __shfl_xor_sync(0xffffffffu, m, 1));
    float sum = 0.f;
    #pragma unroll
    for (int j = 0; j < 8; j++) { sc[j] = __expf(sc[j] - m); sum += sc[j]; }
    sum += __shfl_xor_sync(0xffffffffu, sum, 1);
    float inv = 1.0f / sum;
    #pragma unroll
    for (int j = 0; j < 8; j++) p[tq * 17 + tk0 + j] = sc[j] * inv;
    __syncwarp();

    // o[t, d2=lane]: loop t; accumulate over tk in fp32; write half2
    for (int t = 0; t < 16; t++) {
        float2 acc = make_float2(0.f, 0.f);
        #pragma unroll
        for (int tk = 0; tk < 16; tk++) {
            float pw = p[t * 17 + tk];
            float2 vf = __half22float2(v[tk * 36 + lane]);
            acc.x += pw * vf.x;
            acc.y += pw * vf.y;
        }
        size_t g = ((size_t)((b * 16 + t) * 1024 + spatial)) * Cc + head * 64;
        *((__half2*)(o + g) + lane) = __floats2half2_rn(acc.x, acc.y);
    }
}

// ---------------------------------------------------------------------------
// Launch
// ---------------------------------------------------------------------------
extern "C" void kernel_launch(void* const* d_in, const int* in_sizes, int n_in,
                              void* d_out, int out_size) {
    const float* x     = (const float*)d_in[0];
    const float* ln1_w = (const float*)d_in[1];
    const float* ln1_b = (const float*)d_in[2];
    const float* Wqkv  = (const float*)d_in[3];
    const float* bqkv  = (const float*)d_in[4];
    const float* ln2_w = (const float*)d_in[5];
    const float* ln2_b = (const float*)d_in[6];
    const float* Wout  = (const float*)d_in[7];
    const float* bout  = (const float*)d_in[8];
    float* out = (float*)d_out;

    constexpr int SMEM_QKV = gemm_smem_bytes<256>();   // 135168
    constexpr int SMEM_OUT = gemm_smem_bytes<128>();   // 81920

    static __half *p_yh = nullptr, *p_qkvh = nullptr, *p_oh = nullptr,
                  *p_wqh = nullptr, *p_woh = nullptr;
    if (!p_yh) {
        cudaGetSymbolAddress((void**)&p_yh, g_yh);
        cudaGetSymbolAddress((void**)&p_qkvh, g_qkvh);
        cudaGetSymbolAddress((void**)&p_oh, g_oh);
        cudaGetSymbolAddress((void**)&p_wqh, g_wqh);
        cudaGetSymbolAddress((void**)&p_woh, g_woh);
        cudaFuncSetAttribute((const void*)gemm_fp16<256, false, true>,
                             cudaFuncAttributeMaxDynamicSharedMemorySize, SMEM_QKV);
        cudaFuncSetAttribute((const void*)gemm_fp16<128, true, false>,
                             cudaFuncAttributeMaxDynamicSharedMemorySize, SMEM_OUT);
    }

    // 0) weights -> half
    {
        int n4q = (F3 * Cc) / 4, n4o = (Cc * Cc) / 4;
        f2h_kernel<<<(n4q + 255) / 256, 256>>>(Wqkv, p_wqh, n4q);
        f2h_kernel<<<(n4o + 255) / 256, 256>>>(Wout, p_woh, n4o);
    }

    // 1) LN1 -> half
    ln_kernel<<<NTOK, 192>>>(x, ln1_w, ln1_b, p_yh);

    // 2) QKV GEMM (half output): (32768 x 2304), BM=256
    {
        dim3 grid(F3 / BN, NTOK / 256);    // 18 x 128
        gemm_fp16<256, false, true><<<grid, 512, SMEM_QKV>>>(
            p_yh, p_wqh, bqkv, nullptr, nullptr, p_qkvh, F3, Cc);
    }

    // 3) Attention (half in/out)
    {
        int nunits = Bb * Hh * Ww * NHh;   // 24576
        attn_kernel<<<nunits / 2, 64>>>(p_qkvh, p_oh);
    }

    // 4) LN2 (half in) -> half y
    ln_h_kernel<<<NTOK, 192>>>(p_oh, ln2_w, ln2_b, p_yh);

    // 5) Out GEMM + bias + residual: (32768 x 768), float output, BM=128
    {
        dim3 grid(Cc / BN, NTOK / 128);    // 6 x 256
        gemm_fp16<128, true, false><<<grid, 256, SMEM_OUT>>>(
            p_yh, p_woh, bout, x, out, nullptr, Cc, Cc);
    }
}

// round 17
// speedup vs baseline: 1.1495x; 1.0049x over previous
#include <cuda_runtime.h>
#include <cstdint>
#include <cuda_fp16.h>
#include <mma.h>
using namespace nvcuda;

// Problem constants
#define Bb 2
#define Tt 16
#define Hh 32
#define Ww 32
#define Cc 768
#define NHh 12
#define HDd 64
#define NTOK (Bb*Tt*Hh*Ww)      // 32768
#define F3 (3*Cc)               // 2304

// Scratch (no allocations allowed — device globals)
__device__ __half g_yh[NTOK * Cc];      // LN output (half)
__device__ __half g_qkvh[NTOK * F3];    // QKV GEMM output (half)
__device__ __half g_wqh[F3 * Cc];       // half Wqkv
__device__ __half g_woh[Cc * Cc];       // half Wout

// ---------------------------------------------------------------------------
// float -> half conversion pre-pass
// ---------------------------------------------------------------------------
__global__ void f2h_kernel(const float* __restrict__ in,
                           __half* __restrict__ out, int n4) {
    int i = blockIdx.x * 256 + threadIdx.x;
    if (i < n4) {
        float4 v = ((const float4*)in)[i];
        ((__half2*)out)[2 * i]     = __floats2half2_rn(v.x, v.y);
        ((__half2*)out)[2 * i + 1] = __floats2half2_rn(v.z, v.w);
    }
}

// ---------------------------------------------------------------------------
// LayerNorm (float input): one block (192 threads) per token; half output
// ---------------------------------------------------------------------------
__global__ void ln_kernel(const float* __restrict__ x,
                          const float* __restrict__ w,
                          const float* __restrict__ b,
                          __half* __restrict__ y) {
    int tok = blockIdx.x;
    int t = threadIdx.x;
    const float4* xr = (const float4*)(x + (size_t)tok * Cc);
    __half2* yr = (__half2*)(y + (size_t)tok * Cc);

    float4 v = xr[t];
    float s  = v.x + v.y + v.z + v.w;
    float ss = v.x*v.x + v.y*v.y + v.z*v.z + v.w*v.w;

    __shared__ float reds[6], redss[6];
    #pragma unroll
    for (int o = 16; o; o >>= 1) {
        s  += __shfl_xor_sync(0xffffffffu, s,  o);
        ss += __shfl_xor_sync(0xffffffffu, ss, o);
    }
    int wid = t >> 5, lid = t & 31;
    if (lid == 0) { reds[wid] = s; redss[wid] = ss; }
    __syncthreads();
    if (t < 32) {
        s  = (lid < 6) ? reds[lid]  : 0.f;
        ss = (lid < 6) ? redss[lid] : 0.f;
        #pragma unroll
        for (int o = 4; o; o >>= 1) {
            s  += __shfl_xor_sync(0xffffffffu, s,  o);
            ss += __shfl_xor_sync(0xffffffffu, ss, o);
        }
        if (lid == 0) { reds[0] = s; redss[0] = ss; }
    }
    __syncthreads();
    float mu  = reds[0] * (1.0f / Cc);
    float var = redss[0] * (1.0f / Cc) - mu * mu;
    float rstd = rsqrtf(var + 1e-5f);

    float4 wv = ((const float4*)w)[t];
    float4 bv = ((const float4*)b)[t];
    float rx = (v.x - mu) * rstd * wv.x + bv.x;
    float ry = (v.y - mu) * rstd * wv.y + bv.y;
    float rz = (v.z - mu) * rstd * wv.z + bv.z;
    float rw = (v.w - mu) * rstd * wv.w + bv.w;
    yr[2 * t]     = __floats2half2_rn(rx, ry);
    yr[2 * t + 1] = __floats2half2_rn(rz, rw);
}

// ---------------------------------------------------------------------------
// FP16 wmma GEMM (fp32 accumulate), 4-stage cp.async, 1 barrier/iter.
// BMT=128: 8 warps (2m x 4n), 256 thr, 2 CTA/SM.
// BMT=256: 16 warps (4m x 4n), 512 thr, 1 CTA/SM.
// Warp tile 64x32, BK=32 halfs, SSTRH=40.
// ---------------------------------------------------------------------------
#define BN 128
#define BKH 32
#define SSTRH 40
#define LDC 132
#define STAGES 4

__device__ __forceinline__ void cp_async16(void* smem_dst, const void* gmem_src) {
    unsigned s = (unsigned)__cvta_generic_to_shared(smem_dst);
    asm volatile("cp.async.cg.shared.global [%0], [%1], 16;\n" :: "r"(s), "l"(gmem_src));
}
#define CP_COMMIT() asm volatile("cp.async.commit_group;\n" ::: "memory")
#define CP_WAIT_N(n) asm volatile("cp.async.wait_group %0;\n" :: "n"(n) : "memory")

template <int BMT>
constexpr int gemm_smem_bytes() {
    int pipe = STAGES * (BMT + BN) * SSTRH * 2;
    int epi = BMT * LDC * 4;
    return pipe > epi ? pipe : epi;
}

template <int BMT, bool RES, bool OUTH>
__global__ void __launch_bounds__(BMT * 2, BMT == 128 ? 2 : 1) gemm_fp16(
        const __half* __restrict__ A,
        const __half* __restrict__ Wt,
        const float* __restrict__ bias,
        const float* __restrict__ res,
        float* __restrict__ Cout,
        __half* __restrict__ CoutH,
        int N, int K) {
    constexpr int NTHR = BMT * 2;
    constexpr int STAGE_H = (BMT + BN) * SSTRH;
    extern __shared__ __align__(16) char smem_raw[];
    __half* hs = (__half*)smem_raw;

    int tid = threadIdx.x;
    int m0 = blockIdx.y * BMT;
    int n0 = blockIdx.x * BN;

    int wid = tid >> 5;
    int wm, wn;
    if (BMT == 128) { wm = (wid & 1) * 64; wn = (wid >> 1) * 32; }
    else            { wm = (wid & 3) * 64; wn = (wid >> 2) * 32; }

    // Loader mapping
    int lrow, lc0, arow0, aco;
    const __half *Ab0, *Ab1, *Bb0;
    if (BMT == 128) {
        lrow = tid >> 1; lc0 = (tid & 1) * 2;
        Ab0 = A  + (size_t)(m0 + lrow) * K + lc0 * 8;
        Bb0 = Wt + (size_t)(n0 + lrow) * K + lc0 * 8;
        Ab1 = nullptr; arow0 = 0; aco = 0;
    } else {
        arow0 = tid >> 2; aco = (tid & 3) * 8;
        Ab0 = A  + (size_t)(m0 + arow0) * K + aco;
        Ab1 = A  + (size_t)(m0 + arow0 + 128) * K + aco;
        Bb0 = Wt + (size_t)(n0 + arow0) * K + aco;
        lrow = 0; lc0 = 0;
    }

    wmma::fragment<wmma::accumulator, 16, 16, 16, float> acc[4][2];
    #pragma unroll
    for (int i = 0; i < 4; i++)
        #pragma unroll
        for (int j = 0; j < 2; j++)
            wmma::fill_fragment(acc[i][j], 0.0f);

    const int nit = K / BKH;             // 24

    #pragma unroll
    for (int s = 0; s < STAGES - 1; s++) {
        __half* abase = hs + s * STAGE_H;
        __half* bbase = abase + BMT * SSTRH;
        int ko = s * BKH;
        if (BMT == 128) {
            __half* a = abase + lrow * SSTRH + lc0 * 8;
            __half* b = bbase + lrow * SSTRH + lc0 * 8;
            #pragma unroll
            for (int c = 0; c < 2; c++) {
                cp_async16(a + c * 8, Ab0 + ko + c * 8);
                cp_async16(b + c * 8, Bb0 + ko + c * 8);
            }
        } else {
            cp_async16(abase + arow0 * SSTRH + aco,         Ab0 + ko);
            cp_async16(abase + (arow0 + 128) * SSTRH + aco, Ab1 + ko);
            cp_async16(bbase + arow0 * SSTRH + aco,         Bb0 + ko);
        }
        CP_COMMIT();
    }

    int sc_ = 0, sl_ = STAGES - 1;
    for (int it = 0; it < nit; it++) {
        CP_WAIT_N(STAGES - 2);
        __syncthreads();

        if (it + STAGES - 1 < nit) {
            __half* abase = hs + sl_ * STAGE_H;
            __half* bbase = abase + BMT * SSTRH;
            int ko = (it + STAGES - 1) * BKH;
            if (BMT == 128) {
                __half* a = abase + lrow * SSTRH + lc0 * 8;
                __half* b = bbase + lrow * SSTRH + lc0 * 8;
                #pragma unroll
                for (int c = 0; c < 2; c++) {
                    cp_async16(a + c * 8, Ab0 + ko + c * 8);
                    cp_async16(b + c * 8, Bb0 + ko + c * 8);
                }
            } else {
                cp_async16(abase + arow0 * SSTRH + aco,         Ab0 + ko);
                cp_async16(abase + (arow0 + 128) * SSTRH + aco, Ab1 + ko);
                cp_async16(bbase + arow0 * SSTRH + aco,         Bb0 + ko);
            }
        }
        CP_COMMIT();

        __half* Ac = hs + sc_ * STAGE_H;
        __half* Bc = Ac + BMT * SSTRH;
        #pragma unroll
        for (int kk = 0; kk < BKH; kk += 16) {
            wmma::fragment<wmma::matrix_a, 16, 16, 16, __half, wmma::row_major> af[4];
            wmma::fragment<wmma::matrix_b, 16, 16, 16, __half, wmma::col_major> bf[2];
            #pragma unroll
            for (int i = 0; i < 4; i++)
                wmma::load_matrix_sync(af[i], &Ac[(wm + i * 16) * SSTRH + kk], SSTRH);
            #pragma unroll
            for (int j = 0; j < 2; j++)
                wmma::load_matrix_sync(bf[j], &Bc[(wn + j * 16) * SSTRH + kk], SSTRH);
            #pragma unroll
            for (int i = 0; i < 4; i++)
                #pragma unroll
                for (int j = 0; j < 2; j++)
                    wmma::mma_sync(acc[i][j], af[i], bf[j], acc[i][j]);
        }

        sc_ = (sc_ + 1 == STAGES) ? 0 : sc_ + 1;
        sl_ = (sl_ + 1 == STAGES) ? 0 : sl_ + 1;
    }
    CP_WAIT_N(0);
    __syncthreads();

    // Epilogue through shared (fp32)
    float* Cs = (float*)smem_raw;
    #pragma unroll
    for (int i = 0; i < 4; i++)
        #pragma unroll
        for (int j = 0; j < 2; j++)
            wmma::store_matrix_sync(&Cs[(wm + i * 16) * LDC + wn + j * 16],
                                    acc[i][j], LDC, wmma::mem_row_major);
    __syncthreads();

    if (OUTH) {
        #pragma unroll
        for (int i = 0; i < 32; i++) {
            int idx = tid + i * NTHR;
            int r = idx >> 6, c2 = idx & 63;
            float2 cs = *(const float2*)&Cs[r * LDC + c2 * 2];
            float2 bv = *(const float2*)(bias + n0 + c2 * 2);
            __half2 hv = __floats2half2_rn(cs.x + bv.x, cs.y + bv.y);
            *((__half2*)(CoutH + (size_t)(m0 + r) * N + n0) + c2) = hv;
        }
    } else {
        #pragma unroll
        for (int i = 0; i < 16; i++) {
            int idx = tid + i * NTHR;
            int r = idx >> 5, c4 = idx & 31;
            const float* cs = &Cs[r * LDC + c4 * 4];
            float4 bv = *(const float4*)(bias + n0 + c4 * 4);
            float4 v;
            v.x = cs[0] + bv.x; v.y = cs[1] + bv.y;
            v.z = cs[2] + bv.z; v.w = cs[3] + bv.w;
            size_t g = (size_t)(m0 + r) * N + n0 + c4 * 4;
            if (RES) {
                float4 rv = *(const float4*)(res + g);
                v.x += rv.x; v.y += rv.y; v.z += rv.z; v.w += rv.w;
            }
            *(float4*)(Cout + g) = v;
        }
    }
}

// ---------------------------------------------------------------------------
// Fused attention + LayerNorm2, occupancy-safe (o in registers).
// One block per (b,h,w): 12 warps, one per head. T=16, HD=64.
// smem: qkv stage (83KB) + probs (13KB) + stats (1.6KB) -> 2 CTAs/SM.
// ---------------------------------------------------------------------------
#define AT_THREADS 384
#define QKV_H2 (12 * 16 * 36)               // per tensor, in half2 units
#define ATTN_SMEM_BYTES (3 * QKV_H2 * 4 + 12 * 16 * 17 * 4 + (2 * 12 * 16 + 32) * 4)

__global__ void __launch_bounds__(AT_THREADS, 2) attn_ln2_kernel(
        const __half* __restrict__ qkv,
        const float* __restrict__ ln2w,
        const float* __restrict__ ln2b,
        __half* __restrict__ y) {
    extern __shared__ __align__(16) char sm_raw[];
    __half2* qs = (__half2*)sm_raw;               // [12][16][36]
    __half2* ks = qs + QKV_H2;
    __half2* vs = ks + QKV_H2;
    float* ps    = (float*)(vs + QKV_H2);         // [12][16][17]
    float* psum  = ps + 12 * 16 * 17;             // [12][16]
    float* psq   = psum + 12 * 16;                // [12][16]
    float* mus   = psq + 12 * 16;                 // [16]
    float* rstds = mus + 16;                      // [16]

    int tid = threadIdx.x;
    int h = tid >> 5;        // head (warp)
    int lane = tid & 31;
    int sp = blockIdx.x;     // b*1024 + spatial
    int b = sp >> 10;
    int spatial = sp & 1023;

    // Stage q,k,v for this head (16 rows x 32 half2 each)
    for (int i = lane; i < 16 * 32; i += 32) {
        int t = i >> 5, d2 = i & 31;
        size_t g = ((size_t)((b * 16 + t) * 1024 + spatial)) * F3 + h * 192;
        const __half2* p2 = (const __half2*)(qkv + g);
        qs[(h * 16 + t) * 36 + d2] = p2[d2];
        ks[(h * 16 + t) * 36 + d2] = p2[32 + d2];
        vs[(h * 16 + t) * 36 + d2] = p2[64 + d2];
    }
    __syncwarp();

    // Scores: lane pair per tq; each lane 8 tk
    int tq = lane >> 1;
    int tk0 = (lane & 1) * 8;
    float sc[8];
    #pragma unroll
    for (int j = 0; j < 8; j++) {
        float acc = 0.f;
        #pragma unroll
        for (int d2 = 0; d2 < 32; d2++) {
            float2 qf = __half22float2(qs[(h * 16 + tq) * 36 + d2]);
            float2 kf = __half22float2(ks[(h * 16 + tk0 + j) * 36 + d2]);
            acc += qf.x * kf.x + qf.y * kf.y;
        }
        sc[j] = acc * 0.125f;
    }
    float m = sc[0];
    #pragma unroll
    for (int j = 1; j < 8; j++) m = fmaxf(m, sc[j]);
    m = fmaxf(m, __shfl_xor_sync(0xffffffffu, m, 1));
    float sum = 0.f;
    #pragma unroll
    for (int j = 0; j < 8; j++) { sc[j] = __expf(sc[j] - m); sum += sc[j]; }
    sum += __shfl_xor_sync(0xffffffffu, sum, 1);
    float inv = 1.0f / sum;
    #pragma unroll
    for (int j = 0; j < 8; j++) ps[(h * 16 + tq) * 17 + tk0 + j] = sc[j] * inv;
    __syncwarp();

    // o[t, d2=lane] in registers; per-token partial sums for LN2
    float2 oreg[16];
    #pragma unroll
    for (int t = 0; t < 16; t++) {
        float2 acc = make_float2(0.f, 0.f);
        #pragma unroll
        for (int tk = 0; tk < 16; tk++) {
            float pw = ps[(h * 16 + t) * 17 + tk];
            float2 vf = __half22float2(vs[(h * 16 + tk) * 36 + lane]);
            acc.x += pw * vf.x;
            acc.y += pw * vf.y;
        }
        oreg[t] = acc;
        float s  = acc.x + acc.y;
        float ss = acc.x * acc.x + acc.y * acc.y;
        #pragma unroll
        for (int o = 16; o; o >>= 1) {
            s  += __shfl_xor_sync(0xffffffffu, s,  o);
            ss += __shfl_xor_sync(0xffffffffu, ss, o);
        }
        if (lane == 0) { psum[h * 16 + t] = s; psq[h * 16 + t] = ss; }
    }
    __syncthreads();

    // LN2 stats per token (threads 0..15)
    if (tid < 16) {
        float s = 0.f, ss = 0.f;
        #pragma unroll
        for (int hh = 0; hh < 12; hh++) {
            s  += psum[hh * 16 + tid];
            ss += psq[hh * 16 + tid];
        }
        float mu = s * (1.0f / Cc);
        float var = ss * (1.0f / Cc) - mu * mu;
        mus[tid] = mu;
        rstds[tid] = rsqrtf(var + 1e-5f);
    }
    __syncthreads();

    // Normalize registers and write y (half)
    float2 w2 = *(const float2*)(ln2w + h * 64 + lane * 2);
    float2 b2 = *(const float2*)(ln2b + h * 64 + lane * 2);
    #pragma unroll
    for (int t = 0; t < 16; t++) {
        float mu = mus[t], rs = rstds[t];
        float r0 = (oreg[t].x - mu) * rs * w2.x + b2.x;
        float r1 = (oreg[t].y - mu) * rs * w2.y + b2.y;
        size_t g = ((size_t)((b * 16 + t) * 1024 + spatial)) * Cc + h * 64;
        *((__half2*)(y + g) + lane) = __floats2half2_rn(r0, r1);
    }
}

// ---------------------------------------------------------------------------
// Launch
// ---------------------------------------------------------------------------
extern "C" void kernel_launch(void* const* d_in, const int* in_sizes, int n_in,
                              void* d_out, int out_size) {
    const float* x     = (const float*)d_in[0];
    const float* ln1_w = (const float*)d_in[1];
    const float* ln1_b = (const float*)d_in[2];
    const float* Wqkv  = (const float*)d_in[3];
    const float* bqkv  = (const float*)d_in[4];
    const float* ln2_w = (const float*)d_in[5];
    const float* ln2_b = (const float*)d_in[6];
    const float* Wout  = (const float*)d_in[7];
    const float* bout  = (const float*)d_in[8];
    float* out = (float*)d_out;

    constexpr int SMEM_QKV = gemm_smem_bytes<256>();   // 135168
    constexpr int SMEM_OUT = gemm_smem_bytes<128>();   // 81920

    static __half *p_yh = nullptr, *p_qkvh = nullptr,
                  *p_wqh = nullptr, *p_woh = nullptr;
    if (!p_yh) {
        cudaGetSymbolAddress((void**)&p_yh, g_yh);
        cudaGetSymbolAddress((void**)&p_qkvh, g_qkvh);
        cudaGetSymbolAddress((void**)&p_wqh, g_wqh);
        cudaGetSymbolAddress((void**)&p_woh, g_woh);
        cudaFuncSetAttribute((const void*)gemm_fp16<256, false, true>,
                             cudaFuncAttributeMaxDynamicSharedMemorySize, SMEM_QKV);
        cudaFuncSetAttribute((const void*)gemm_fp16<128, true, false>,
                             cudaFuncAttributeMaxDynamicSharedMemorySize, SMEM_OUT);
        cudaFuncSetAttribute((const void*)attn_ln2_kernel,
                             cudaFuncAttributeMaxDynamicSharedMemorySize, ATTN_SMEM_BYTES);
    }

    // 0) weights -> half
    {
        int n4q = (F3 * Cc) / 4, n4o = (Cc * Cc) / 4;
        f2h_kernel<<<(n4q + 255) / 256, 256>>>(Wqkv, p_wqh, n4q);
        f2h_kernel<<<(n4o + 255) / 256, 256>>>(Wout, p_woh, n4o);
    }

    // 1) LN1 -> half
    ln_kernel<<<NTOK, 192>>>(x, ln1_w, ln1_b, p_yh);

    // 2) QKV GEMM (half output): (32768 x 2304), BM=256
    {
        dim3 grid(F3 / BN, NTOK / 256);    // 18 x 128
        gemm_fp16<256, false, true><<<grid, 512, SMEM_QKV>>>(
            p_yh, p_wqh, bqkv, nullptr, nullptr, p_qkvh, F3, Cc);
    }

    // 3) Fused attention + LN2 -> half y
    {
        attn_ln2_kernel<<<Bb * Hh * Ww, AT_THREADS, ATTN_SMEM_BYTES>>>(
            p_qkvh, ln2_w, ln2_b, p_yh);
    }

    // 4) Out GEMM + bias + residual: (32768 x 768), float output, BM=128
    {
        dim3 grid(Cc / BN, NTOK / 128);    // 6 x 256
        gemm_fp16<128, true, false><<<grid, 256, SMEM_OUT>>>(
            p_yh, p_woh, bout, x, out, nullptr, Cc, Cc);
    }
}